// round 1
// baseline (speedup 1.0000x reference)
#include <cuda_runtime.h>
#include <math.h>

// Fixed problem shapes
#define NH 3        // heads
#define NB 16       // batch
#define NN 1024     // nodes (== F_)
#define NF 512      // input features
#define NFP 1024    // output features

// Scratch (device globals; no allocation allowed)
__device__ float g_feats[(size_t)NH * NB * NN * NFP];   // 192 MiB
__device__ float g_sself[NH * NB * NN];
__device__ float g_sneigh[NH * NB * NN];
__device__ float g_biasmean[NFP];

// ---------------------------------------------------------------------------
// Kernel 1: feats[h,b] = x[b] (1024x512) @ kernels[h] (512x1024)
// Classic SGEMM: 128x128 tile, BK=8, 256 threads, 8x8 per-thread register tile
// ---------------------------------------------------------------------------
__global__ __launch_bounds__(256, 2) void feats_gemm(
    const float* __restrict__ x, const float* __restrict__ kern)
{
    const int hb = blockIdx.z;          // 0..47
    const int h  = hb >> 4;             // /16
    const int b  = hb & 15;
    const float* A  = x    + (size_t)b  * NN * NF;   // [NN, NF] lda=NF
    const float* Bm = kern + (size_t)h  * NF * NFP;  // [NF, NFP] ldb=NFP
    float*       C  = g_feats + (size_t)hb * NN * NFP;

    __shared__ float As[8][128];
    __shared__ float Bs[8][128];

    const int tid  = threadIdx.x;
    const int tr   = tid >> 4;          // 0..15
    const int tc   = tid & 15;          // 0..15
    const int row0 = blockIdx.y * 128;
    const int col0 = blockIdx.x * 128;

    const int arow = tid >> 1;          // 0..127
    const int ak   = (tid & 1) * 4;     // 0 or 4
    const int bk   = tid >> 5;          // 0..7
    const int bcol = (tid & 31) * 4;    // 0..124

    float acc[8][8];
#pragma unroll
    for (int i = 0; i < 8; i++)
#pragma unroll
        for (int j = 0; j < 8; j++) acc[i][j] = 0.f;

    for (int kt = 0; kt < NF; kt += 8) {
        float4 av = *(const float4*)(A + (size_t)(row0 + arow) * NF + kt + ak);
        As[ak + 0][arow] = av.x;
        As[ak + 1][arow] = av.y;
        As[ak + 2][arow] = av.z;
        As[ak + 3][arow] = av.w;
        *(float4*)&Bs[bk][bcol] =
            *(const float4*)(Bm + (size_t)(kt + bk) * NFP + col0 + bcol);
        __syncthreads();
#pragma unroll
        for (int kk = 0; kk < 8; kk++) {
            float a[8], bb[8];
#pragma unroll
            for (int i = 0; i < 8; i++) a[i] = As[kk][tr * 8 + i];
#pragma unroll
            for (int j = 0; j < 8; j++) bb[j] = Bs[kk][tc * 8 + j];
#pragma unroll
            for (int i = 0; i < 8; i++)
#pragma unroll
                for (int j = 0; j < 8; j++)
                    acc[i][j] = fmaf(a[i], bb[j], acc[i][j]);
        }
        __syncthreads();
    }

#pragma unroll
    for (int i = 0; i < 8; i++) {
        float4* p = (float4*)(C + (size_t)(row0 + tr * 8 + i) * NFP + col0 + tc * 8);
        p[0] = make_float4(acc[i][0], acc[i][1], acc[i][2], acc[i][3]);
        p[1] = make_float4(acc[i][4], acc[i][5], acc[i][6], acc[i][7]);
    }
}

// ---------------------------------------------------------------------------
// Kernel 2: s_self[r] = feats_row . attn_self[h], s_neigh likewise.
// One warp per row (r over H*B*N), 8 warps / block.
// ---------------------------------------------------------------------------
__global__ __launch_bounds__(256) void s_reduce(
    const float* __restrict__ aself, const float* __restrict__ aneigh)
{
    const int w    = threadIdx.x >> 5;
    const int lane = threadIdx.x & 31;
    const size_t r = (size_t)blockIdx.x * 8 + w;       // 0..49151
    const int h    = (int)(r >> 14);                    // r / (NB*NN)
    const float* f  = g_feats + r * NFP;
    const float* as = aself  + (size_t)h * NFP;
    const float* an = aneigh + (size_t)h * NFP;

    float s1 = 0.f, s2 = 0.f;
#pragma unroll
    for (int it = 0; it < 8; it++) {
        int k = it * 128 + lane * 4;
        float4 fv = *(const float4*)(f + k);
        float4 a1 = *(const float4*)(as + k);
        float4 a2 = *(const float4*)(an + k);
        s1 += fv.x * a1.x + fv.y * a1.y + fv.z * a1.z + fv.w * a1.w;
        s2 += fv.x * a2.x + fv.y * a2.y + fv.z * a2.z + fv.w * a2.w;
    }
#pragma unroll
    for (int o = 16; o > 0; o >>= 1) {
        s1 += __shfl_xor_sync(0xFFFFFFFFu, s1, o);
        s2 += __shfl_xor_sync(0xFFFFFFFFu, s2, o);
    }
    if (lane == 0) { g_sself[r] = s1; g_sneigh[r] = s2; }
}

// ---------------------------------------------------------------------------
// Kernel 3: attn row softmax. attn[r, j] = softmax_j(leaky(s_self[r] + s_neigh[hb, j]))
// One warp per row; the row's 1024 logits live in 32 registers/lane.
// Writes directly into d_out (attn occupies the first H*B*N*N elements).
// ---------------------------------------------------------------------------
__global__ __launch_bounds__(256) void attn_softmax(float* __restrict__ out)
{
    __shared__ float c[NN];
    const int w    = threadIdx.x >> 5;
    const int lane = threadIdx.x & 31;
    const size_t r0 = (size_t)blockIdx.x * 8;   // 8 rows, all same (h,b)
    const size_t hb = r0 >> 10;                 // r0 / NN
    const float* cn = g_sneigh + hb * NN;
    for (int i = threadIdx.x; i < NN; i += 256) c[i] = cn[i];
    __syncthreads();

    const size_t r = r0 + w;
    const float a = g_sself[r];

    float ev[32];
    float m = -1e30f;
#pragma unroll
    for (int it = 0; it < 32; it++) {
        float t = a + c[it * 32 + lane];
        t = (t >= 0.f) ? t : 0.2f * t;
        ev[it] = t;
        m = fmaxf(m, t);
    }
#pragma unroll
    for (int o = 16; o > 0; o >>= 1) m = fmaxf(m, __shfl_xor_sync(0xFFFFFFFFu, m, o));

    float s = 0.f;
#pragma unroll
    for (int it = 0; it < 32; it++) {
        float e = __expf(ev[it] - m);
        ev[it] = e;
        s += e;
    }
#pragma unroll
    for (int o = 16; o > 0; o >>= 1) s += __shfl_xor_sync(0xFFFFFFFFu, s, o);
    const float inv = 1.f / s;

    float* orow = out + r * NN;
#pragma unroll
    for (int it = 0; it < 32; it++) orow[it * 32 + lane] = ev[it] * inv;
}

// ---------------------------------------------------------------------------
// Kernel 4a: bias mean over heads
// ---------------------------------------------------------------------------
__global__ void bias_mean(const float* __restrict__ biases)
{
    int k = blockIdx.x * 256 + threadIdx.x;
    g_biasmean[k] =
        (biases[k] + biases[NFP + k] + biases[2 * NFP + k]) * (1.f / 3.f);
}

// ---------------------------------------------------------------------------
// Kernel 4: out[b] = (1/3) * sum_h attn[h,b] @ feats[h,b] + bias_mean
// Same SGEMM tiling, K fused over heads (effective K = 3*1024).
// attn is read from d_out; output written to d_out slice [3].
// ---------------------------------------------------------------------------
__global__ __launch_bounds__(256, 2) void out_gemm(
    const float* __restrict__ attn, float* __restrict__ out)
{
    const int b = blockIdx.z;
    float* C = out + (size_t)(3 * NB + b) * NN * NN;

    __shared__ float As[8][128];
    __shared__ float Bs[8][128];

    const int tid  = threadIdx.x;
    const int tr   = tid >> 4;
    const int tc   = tid & 15;
    const int row0 = blockIdx.y * 128;
    const int col0 = blockIdx.x * 128;

    const int arow = tid >> 1;
    const int ak   = (tid & 1) * 4;
    const int bk   = tid >> 5;
    const int bcol = (tid & 31) * 4;

    float acc[8][8];
#pragma unroll
    for (int i = 0; i < 8; i++)
#pragma unroll
        for (int j = 0; j < 8; j++) acc[i][j] = 0.f;

    for (int h = 0; h < NH; h++) {
        const float* A  = attn    + (size_t)(h * NB + b) * NN * NN;   // lda=NN
        const float* Bm = g_feats + (size_t)(h * NB + b) * NN * NFP;  // ldb=NFP
        for (int kt = 0; kt < NN; kt += 8) {
            float4 av = *(const float4*)(A + (size_t)(row0 + arow) * NN + kt + ak);
            As[ak + 0][arow] = av.x;
            As[ak + 1][arow] = av.y;
            As[ak + 2][arow] = av.z;
            As[ak + 3][arow] = av.w;
            *(float4*)&Bs[bk][bcol] =
                *(const float4*)(Bm + (size_t)(kt + bk) * NFP + col0 + bcol);
            __syncthreads();
#pragma unroll
            for (int kk = 0; kk < 8; kk++) {
                float a[8], bb[8];
#pragma unroll
                for (int i = 0; i < 8; i++) a[i] = As[kk][tr * 8 + i];
#pragma unroll
                for (int j = 0; j < 8; j++) bb[j] = Bs[kk][tc * 8 + j];
#pragma unroll
                for (int i = 0; i < 8; i++)
#pragma unroll
                    for (int j = 0; j < 8; j++)
                        acc[i][j] = fmaf(a[i], bb[j], acc[i][j]);
            }
            __syncthreads();
        }
    }

#pragma unroll
    for (int i = 0; i < 8; i++) {
        float bm0 = g_biasmean[col0 + tc * 8 + 0];
        float4 v0 = make_float4(acc[i][0] * (1.f / 3.f) + g_biasmean[col0 + tc * 8 + 0],
                                acc[i][1] * (1.f / 3.f) + g_biasmean[col0 + tc * 8 + 1],
                                acc[i][2] * (1.f / 3.f) + g_biasmean[col0 + tc * 8 + 2],
                                acc[i][3] * (1.f / 3.f) + g_biasmean[col0 + tc * 8 + 3]);
        float4 v1 = make_float4(acc[i][4] * (1.f / 3.f) + g_biasmean[col0 + tc * 8 + 4],
                                acc[i][5] * (1.f / 3.f) + g_biasmean[col0 + tc * 8 + 5],
                                acc[i][6] * (1.f / 3.f) + g_biasmean[col0 + tc * 8 + 6],
                                acc[i][7] * (1.f / 3.f) + g_biasmean[col0 + tc * 8 + 7]);
        (void)bm0;
        float4* p = (float4*)(C + (size_t)(row0 + tr * 8 + i) * NN + col0 + tc * 8);
        p[0] = v0;
        p[1] = v1;
    }
}

// ---------------------------------------------------------------------------
extern "C" void kernel_launch(void* const* d_in, const int* in_sizes, int n_in,
                              void* d_out, int out_size)
{
    const float* x      = (const float*)d_in[0];  // (16,1024,512)
    const float* kern   = (const float*)d_in[1];  // (3,512,1024)
    const float* biases = (const float*)d_in[2];  // (3,1024)
    const float* aself  = (const float*)d_in[3];  // (3,1024)
    const float* aneigh = (const float*)d_in[4];  // (3,1024)
    float* out = (float*)d_out;                   // (4,16,1024,1024)

    dim3 g1(NFP / 128, NN / 128, NH * NB);
    feats_gemm<<<g1, 256>>>(x, kern);

    s_reduce<<<(NH * NB * NN) / 8, 256>>>(aself, aneigh);

    attn_softmax<<<(NH * NB * NN) / 8, 256>>>(out);

    bias_mean<<<NFP / 256, 256>>>(biases);

    dim3 g4(NN / 128, NN / 128, NB);
    out_gemm<<<g4, 256>>>(out, out);
}

// round 3
// speedup vs baseline: 2.7157x; 2.7157x over previous
#include <cuda_runtime.h>
#include <cuda_bf16.h>
#include <stdint.h>

#define NH 3
#define NB 16
#define NN 1024
#define NF 512
#define NFP 1024

// ---------------------------------------------------------------------------
// Scratch arena (device global; all offsets 16B-aligned)
// ---------------------------------------------------------------------------
#define OFF_XHI   0ull
#define OFF_XLO   16777216ull
#define OFF_KTHI  33554432ull
#define OFF_KTLO  36700160ull
#define OFF_FTHI  39845888ull
#define OFF_FTLO  140509184ull
#define OFF_AHI   241172480ull
#define OFF_ALO   341835776ull
#define OFF_W2S   442499072ull
#define OFF_W2N   442505216ull
#define OFF_SS    442511360ull
#define OFF_SN    442707968ull
#define OFF_BM    442904576ull
#define ARENA_SZ  442908672ull

__device__ __align__(128) unsigned char g_arena[ARENA_SZ];
#define AP(T, off) ((T*)(g_arena + (off)))

// ---------------------------------------------------------------------------
// PTX helpers (base sm_103 target: ldmatrix / mma.sync / cp.async only)
// ---------------------------------------------------------------------------
__device__ __forceinline__ uint32_t smem_u32(const void* p) {
    uint32_t a;
    asm("{ .reg .u64 t; cvta.to.shared.u64 t, %1; cvt.u32.u64 %0, t; }"
        : "=r"(a) : "l"(p));
    return a;
}

__device__ __forceinline__ void cpasync16(uint32_t s, const void* g) {
    asm volatile("cp.async.cg.shared.global [%0], [%1], 16;"
                 :: "r"(s), "l"(g) : "memory");
}
__device__ __forceinline__ void cp_commit() {
    asm volatile("cp.async.commit_group;" ::: "memory");
}
template <int N>
__device__ __forceinline__ void cp_wait() {
    asm volatile("cp.async.wait_group %0;" :: "n"(N) : "memory");
}

__device__ __forceinline__ void ldsm4(uint32_t* r, uint32_t a) {
    asm volatile("ldmatrix.sync.aligned.m8n8.x4.shared.b16 {%0,%1,%2,%3}, [%4];"
                 : "=r"(r[0]), "=r"(r[1]), "=r"(r[2]), "=r"(r[3]) : "r"(a));
}
__device__ __forceinline__ void ldsm2(uint32_t* r, uint32_t a) {
    asm volatile("ldmatrix.sync.aligned.m8n8.x2.shared.b16 {%0,%1}, [%2];"
                 : "=r"(r[0]), "=r"(r[1]) : "r"(a));
}

__device__ __forceinline__ void mma16816(float* c, const uint32_t* a,
                                         const uint32_t* b) {
    asm volatile(
        "mma.sync.aligned.m16n8k16.row.col.f32.bf16.bf16.f32 "
        "{%0,%1,%2,%3}, {%4,%5,%6,%7}, {%8,%9}, {%0,%1,%2,%3};"
        : "+f"(c[0]), "+f"(c[1]), "+f"(c[2]), "+f"(c[3])
        : "r"(a[0]), "r"(a[1]), "r"(a[2]), "r"(a[3]), "r"(b[0]), "r"(b[1]));
}

// ---------------------------------------------------------------------------
// GEMM core: 128x128 CTA tile, K-chunk 32 bf16, 2-stage cp.async pipeline.
// A[m][k], B[n][k] both K-major. 3 products: AhiBhi + AhiBlo + AloBhi.
// Smem tile: 128 rows x 40 bf16 (80B pitch), 4 tiles/stage = 40960 B.
// ---------------------------------------------------------------------------
#define PITCH   80
#define TILE_B  10240
#define STAGE_B 40960

__device__ __forceinline__ void load_stage(
    uint32_t sb, int tid, int buf,
    const __nv_bfloat16* Ah, const __nv_bfloat16* Al,
    const __nv_bfloat16* Bh, const __nv_bfloat16* Bl, int lda, int ldb)
{
    const uint32_t st = sb + buf * STAGE_B;
#pragma unroll
    for (int it = 0; it < 2; it++) {
        const int idx = it * 256 + tid;
        const int row = idx >> 2;
        const int seg = idx & 3;
        const uint32_t so = row * PITCH + seg * 16;
        cpasync16(st + so,              (const char*)(Ah + (size_t)row * lda) + seg * 16);
        cpasync16(st + TILE_B + so,     (const char*)(Al + (size_t)row * lda) + seg * 16);
        cpasync16(st + 2 * TILE_B + so, (const char*)(Bh + (size_t)row * ldb) + seg * 16);
        cpasync16(st + 3 * TILE_B + so, (const char*)(Bl + (size_t)row * ldb) + seg * 16);
    }
    cp_commit();
}

__device__ __forceinline__ void mma_stage(uint32_t sbuf, int wm, int wn,
                                          int lane, float acc[4][4][4])
{
    const uint32_t Ahb = sbuf;
    const uint32_t Alb = sbuf + TILE_B;
    const uint32_t Bhb = sbuf + 2 * TILE_B;
    const uint32_t Blb = sbuf + 3 * TILE_B;
#pragma unroll
    for (int ks = 0; ks < 2; ks++) {
        uint32_t bh[4][2], bl[4][2];
        const int brow = wn * 32 + (lane & 7);
        const int bcol = ks * 16 + ((lane >> 3) & 1) * 8;
#pragma unroll
        for (int nt = 0; nt < 4; nt++) {
            const uint32_t ao = (uint32_t)(brow + nt * 8) * PITCH + bcol * 2;
            ldsm2(bh[nt], Bhb + ao);
            ldsm2(bl[nt], Blb + ao);
        }
        const int arow = wm * 64 + (lane & 15);
        const int acol = ks * 16 + (lane >> 4) * 8;
#pragma unroll
        for (int mt = 0; mt < 4; mt++) {
            uint32_t ah[4], al[4];
            const uint32_t ao = (uint32_t)(arow + mt * 16) * PITCH + acol * 2;
            ldsm4(ah, Ahb + ao);
            ldsm4(al, Alb + ao);
#pragma unroll
            for (int nt = 0; nt < 4; nt++) {
                mma16816(acc[mt][nt], ah, bh[nt]);
                mma16816(acc[mt][nt], ah, bl[nt]);
                mma16816(acc[mt][nt], al, bh[nt]);
            }
        }
    }
}

// S = total K-stages, SPH = stages per head (head advances A/B by hstA/hstB).
// Ahi/Alo base pointers already offset to (m0, k=0) of head 0; Bhi/Blo to (n0, 0).
template <int S, int SPH>
__device__ __forceinline__ void gemm_core(
    const __nv_bfloat16* Ahi, const __nv_bfloat16* Alo,
    const __nv_bfloat16* Bhi, const __nv_bfloat16* Blo,
    size_t hstA, size_t hstB, int lda, int ldb,
    char* dynsm, float acc[4][4][4])
{
    const int tid = threadIdx.x;
    const int w = tid >> 5, lane = tid & 31;
    const int wm = w & 1, wn = w >> 1;
    const uint32_t sb = smem_u32(dynsm);

#pragma unroll
    for (int mt = 0; mt < 4; mt++)
#pragma unroll
        for (int nt = 0; nt < 4; nt++)
#pragma unroll
            for (int q = 0; q < 4; q++) acc[mt][nt][q] = 0.f;

    // prologue: stage 0
    load_stage(sb, tid, 0, Ahi, Alo, Bhi, Blo, lda, ldb);

    for (int s = 0; s < S; s++) {
        if (s + 1 < S) {
            const int sn = s + 1;
            const int h = sn / SPH;
            const int kt = (sn - h * SPH) * 32;
            load_stage(sb, tid, sn & 1,
                       Ahi + h * hstA + kt, Alo + h * hstA + kt,
                       Bhi + h * hstB + kt, Blo + h * hstB + kt, lda, ldb);
            cp_wait<1>();
        } else {
            cp_wait<0>();
        }
        __syncthreads();
        mma_stage(sb + (s & 1) * STAGE_B, wm, wn, lane, acc);
        __syncthreads();
    }
}

// ---------------------------------------------------------------------------
// feats GEMM (transposed): D[fp][node] = sum_f kT[fp][f] * x[node][f]
// Epilogue: split fp32 -> (hi, lo) bf16 into fT (K-major for the out GEMM).
// ---------------------------------------------------------------------------
__global__ void __launch_bounds__(256, 2) feats_tc() {
    extern __shared__ char dynsm[];
    const int z = blockIdx.z;          // h*NB + b
    const int h = z >> 4, b = z & 15;
    const int m0 = blockIdx.y * 128;   // fp tile
    const int n0 = blockIdx.x * 128;   // node tile

    const __nv_bfloat16* Ahi = AP(__nv_bfloat16, OFF_KTHI) + (size_t)h * NFP * NF + (size_t)m0 * NF;
    const __nv_bfloat16* Alo = AP(__nv_bfloat16, OFF_KTLO) + (size_t)h * NFP * NF + (size_t)m0 * NF;
    const __nv_bfloat16* Bhi = AP(__nv_bfloat16, OFF_XHI)  + (size_t)b * NN * NF + (size_t)n0 * NF;
    const __nv_bfloat16* Blo = AP(__nv_bfloat16, OFF_XLO)  + (size_t)b * NN * NF + (size_t)n0 * NF;

    float acc[4][4][4];
    gemm_core<16, 16>(Ahi, Alo, Bhi, Blo, 0, 0, NF, NF, dynsm, acc);

    const int w = threadIdx.x >> 5, lane = threadIdx.x & 31;
    const int wm = w & 1, wn = w >> 1;
    __nv_bfloat16* fthi = AP(__nv_bfloat16, OFF_FTHI) + (size_t)z * NFP * NN;
    __nv_bfloat16* ftlo = AP(__nv_bfloat16, OFF_FTLO) + (size_t)z * NFP * NN;
#pragma unroll
    for (int mt = 0; mt < 4; mt++)
#pragma unroll
        for (int nt = 0; nt < 4; nt++)
#pragma unroll
            for (int hf = 0; hf < 2; hf++) {
                const int row = m0 + wm * 64 + mt * 16 + (lane >> 2) + hf * 8;
                const int col = n0 + wn * 32 + nt * 8 + (lane & 3) * 2;
                const float v0 = acc[mt][nt][hf * 2 + 0];
                const float v1 = acc[mt][nt][hf * 2 + 1];
                __nv_bfloat16 h0 = __float2bfloat16(v0);
                __nv_bfloat16 h1 = __float2bfloat16(v1);
                __nv_bfloat162 ph; ph.x = h0; ph.y = h1;
                __nv_bfloat162 pl;
                pl.x = __float2bfloat16(v0 - __bfloat162float(h0));
                pl.y = __float2bfloat16(v1 - __bfloat162float(h1));
                *(__nv_bfloat162*)(fthi + (size_t)row * NN + col) = ph;
                *(__nv_bfloat162*)(ftlo + (size_t)row * NN + col) = pl;
            }
}

// ---------------------------------------------------------------------------
// out GEMM: D[node][fp] = sum_h sum_j attn[h,b,node,j] * fT[h,b][fp][j]
// Epilogue: *1/3 + biasmean, fp32 to d_out slice [3].
// ---------------------------------------------------------------------------
__global__ void __launch_bounds__(256, 2) out_tc(float* __restrict__ out) {
    extern __shared__ char dynsm[];
    const int b = blockIdx.z;
    const int m0 = blockIdx.y * 128;   // node tile
    const int n0 = blockIdx.x * 128;   // fp tile

    const size_t o = (size_t)b * NN * NN;
    const size_t hst = (size_t)NB * NN * NN;
    const __nv_bfloat16* Ahi = AP(__nv_bfloat16, OFF_AHI)  + o + (size_t)m0 * NN;
    const __nv_bfloat16* Alo = AP(__nv_bfloat16, OFF_ALO)  + o + (size_t)m0 * NN;
    const __nv_bfloat16* Bhi = AP(__nv_bfloat16, OFF_FTHI) + o + (size_t)n0 * NN;
    const __nv_bfloat16* Blo = AP(__nv_bfloat16, OFF_FTLO) + o + (size_t)n0 * NN;

    float acc[4][4][4];
    gemm_core<96, 32>(Ahi, Alo, Bhi, Blo, hst, hst, NN, NN, dynsm, acc);

    const int w = threadIdx.x >> 5, lane = threadIdx.x & 31;
    const int wm = w & 1, wn = w >> 1;
    const float* bm = AP(float, OFF_BM);
    float* C = out + ((size_t)(NH * NB) + b) * NN * NN;
#pragma unroll
    for (int mt = 0; mt < 4; mt++)
#pragma unroll
        for (int nt = 0; nt < 4; nt++)
#pragma unroll
            for (int hf = 0; hf < 2; hf++) {
                const int row = m0 + wm * 64 + mt * 16 + (lane >> 2) + hf * 8;
                const int col = n0 + wn * 32 + nt * 8 + (lane & 3) * 2;
                float2 v;
                v.x = acc[mt][nt][hf * 2 + 0] * (1.f / 3.f) + bm[col + 0];
                v.y = acc[mt][nt][hf * 2 + 1] * (1.f / 3.f) + bm[col + 1];
                *(float2*)(C + (size_t)row * NN + col) = v;
            }
}

// ---------------------------------------------------------------------------
// Prep kernels (fp32 paths, exact)
// ---------------------------------------------------------------------------
__global__ void prep_x(const float* __restrict__ x) {
    const size_t i = (size_t)blockIdx.x * 256 + threadIdx.x;  // over NB*NN*NF/4
    float4 v = ((const float4*)x)[i];
    union { __nv_bfloat16 h[4]; uint2 u; } hh, ll;
    float c[4] = { v.x, v.y, v.z, v.w };
#pragma unroll
    for (int k = 0; k < 4; k++) {
        __nv_bfloat16 hi = __float2bfloat16(c[k]);
        hh.h[k] = hi;
        ll.h[k] = __float2bfloat16(c[k] - __bfloat162float(hi));
    }
    ((uint2*)AP(unsigned char, OFF_XHI))[i] = hh.u;
    ((uint2*)AP(unsigned char, OFF_XLO))[i] = ll.u;
}

// kernels (H, F=512, F_=1024) -> kT (H, F_=1024, F=512) hi/lo split
__global__ void prep_kT(const float* __restrict__ kern) {
    __shared__ float t[32][33];
    const int h = blockIdx.z;
    const int fp0 = blockIdx.x * 32, f0 = blockIdx.y * 32;
    const float* src = kern + (size_t)h * NF * NFP;
#pragma unroll
    for (int j = 0; j < 4; j++)
        t[threadIdx.y + j * 8][threadIdx.x] =
            src[(size_t)(f0 + threadIdx.y + j * 8) * NFP + fp0 + threadIdx.x];
    __syncthreads();
    __nv_bfloat16* dhi = AP(__nv_bfloat16, OFF_KTHI) + (size_t)h * NFP * NF;
    __nv_bfloat16* dlo = AP(__nv_bfloat16, OFF_KTLO) + (size_t)h * NFP * NF;
#pragma unroll
    for (int j = 0; j < 4; j++) {
        float v = t[threadIdx.x][threadIdx.y + j * 8];
        __nv_bfloat16 hi = __float2bfloat16(v);
        size_t o2 = (size_t)(fp0 + threadIdx.y + j * 8) * NF + f0 + threadIdx.x;
        dhi[o2] = hi;
        dlo[o2] = __float2bfloat16(v - __bfloat162float(hi));
    }
}

// w2[h][f] = sum_fp kernels[h][f][fp] * a[h][fp]
__global__ void w2k(const float* __restrict__ kern,
                    const float* __restrict__ as, const float* __restrict__ an) {
    const int gw = blockIdx.x * 8 + (threadIdx.x >> 5);
    const int lane = threadIdx.x & 31;
    const int h = gw >> 9, f = gw & 511;
    const float* row = kern + ((size_t)h * NF + f) * NFP;
    const float* a1 = as + (size_t)h * NFP;
    const float* a2 = an + (size_t)h * NFP;
    float s1 = 0.f, s2 = 0.f;
#pragma unroll
    for (int it = 0; it < 8; it++) {
        int k = it * 128 + lane * 4;
        float4 kv = *(const float4*)(row + k);
        float4 v1 = *(const float4*)(a1 + k);
        float4 v2 = *(const float4*)(a2 + k);
        s1 += kv.x * v1.x + kv.y * v1.y + kv.z * v1.z + kv.w * v1.w;
        s2 += kv.x * v2.x + kv.y * v2.y + kv.z * v2.z + kv.w * v2.w;
    }
#pragma unroll
    for (int o = 16; o > 0; o >>= 1) {
        s1 += __shfl_xor_sync(0xFFFFFFFFu, s1, o);
        s2 += __shfl_xor_sync(0xFFFFFFFFu, s2, o);
    }
    if (lane == 0) {
        AP(float, OFF_W2S)[(size_t)h * NF + f] = s1;
        AP(float, OFF_W2N)[(size_t)h * NF + f] = s2;
    }
}

// s_self[h,b,n] = x[b,n,:] . w2s[h]; s_neigh likewise (3 heads per warp)
__global__ void __launch_bounds__(256) s_comp(const float* __restrict__ x) {
    __shared__ float ws[NH * NF], wn_[NH * NF];
    for (int i = threadIdx.x; i < NH * NF; i += 256) {
        ws[i]  = AP(float, OFF_W2S)[i];
        wn_[i] = AP(float, OFF_W2N)[i];
    }
    __syncthreads();
    const int gw = blockIdx.x * 8 + (threadIdx.x >> 5);
    const int lane = threadIdx.x & 31;
    const int b = gw >> 10, n = gw & 1023;
    const float* xr = x + ((size_t)b * NN + n) * NF;
    float a[3] = {0.f, 0.f, 0.f}, c[3] = {0.f, 0.f, 0.f};
#pragma unroll
    for (int it = 0; it < 4; it++) {
        int f = it * 128 + lane * 4;
        float4 xv = *(const float4*)(xr + f);
#pragma unroll
        for (int h = 0; h < 3; h++) {
            float4 w = *(const float4*)&ws[h * NF + f];
            float4 u = *(const float4*)&wn_[h * NF + f];
            a[h] += xv.x * w.x + xv.y * w.y + xv.z * w.z + xv.w * w.w;
            c[h] += xv.x * u.x + xv.y * u.y + xv.z * u.z + xv.w * u.w;
        }
    }
#pragma unroll
    for (int h = 0; h < 3; h++) {
#pragma unroll
        for (int o = 16; o > 0; o >>= 1) {
            a[h] += __shfl_xor_sync(0xFFFFFFFFu, a[h], o);
            c[h] += __shfl_xor_sync(0xFFFFFFFFu, c[h], o);
        }
    }
    if (lane == 0) {
#pragma unroll
        for (int h = 0; h < 3; h++) {
            AP(float, OFF_SS)[(size_t)h * NB * NN + b * NN + n] = a[h];
            AP(float, OFF_SN)[(size_t)h * NB * NN + b * NN + n] = c[h];
        }
    }
}

// Row softmax of leaky(s_self[i]+s_neigh[j]); fp32 attn to d_out + hi/lo bf16.
__global__ void __launch_bounds__(256) attn_softmax(float* __restrict__ out) {
    __shared__ float c[NN];
    const int w    = threadIdx.x >> 5;
    const int lane = threadIdx.x & 31;
    const size_t r0 = (size_t)blockIdx.x * 8;
    const size_t hb = r0 >> 10;
    const float* cn = AP(float, OFF_SN) + hb * NN;
    for (int i = threadIdx.x; i < NN; i += 256) c[i] = cn[i];
    __syncthreads();

    const size_t r = r0 + w;
    const float a = AP(float, OFF_SS)[r];

    float ev[32];
    float m = -1e30f;
#pragma unroll
    for (int it = 0; it < 32; it++) {
        float t = a + c[it * 32 + lane];
        t = (t >= 0.f) ? t : 0.2f * t;
        ev[it] = t;
        m = fmaxf(m, t);
    }
#pragma unroll
    for (int o = 16; o > 0; o >>= 1) m = fmaxf(m, __shfl_xor_sync(0xFFFFFFFFu, m, o));
    float s = 0.f;
#pragma unroll
    for (int it = 0; it < 32; it++) {
        float e = __expf(ev[it] - m);
        ev[it] = e;
        s += e;
    }
#pragma unroll
    for (int o = 16; o > 0; o >>= 1) s += __shfl_xor_sync(0xFFFFFFFFu, s, o);
    const float inv = 1.f / s;

    float* orow = out + r * NN;
    __nv_bfloat16* ahi = AP(__nv_bfloat16, OFF_AHI) + r * NN;
    __nv_bfloat16* alo = AP(__nv_bfloat16, OFF_ALO) + r * NN;
#pragma unroll
    for (int it = 0; it < 32; it++) {
        float v = ev[it] * inv;
        int col = it * 32 + lane;
        orow[col] = v;
        __nv_bfloat16 hi = __float2bfloat16(v);
        ahi[col] = hi;
        alo[col] = __float2bfloat16(v - __bfloat162float(hi));
    }
}

__global__ void bias_mean(const float* __restrict__ biases) {
    int k = blockIdx.x * 256 + threadIdx.x;
    AP(float, OFF_BM)[k] =
        (biases[k] + biases[NFP + k] + biases[2 * NFP + k]) * (1.f / 3.f);
}

// ---------------------------------------------------------------------------
extern "C" void kernel_launch(void* const* d_in, const int* in_sizes, int n_in,
                              void* d_out, int out_size)
{
    const float* x      = (const float*)d_in[0];
    const float* kern   = (const float*)d_in[1];
    const float* biases = (const float*)d_in[2];
    const float* aself  = (const float*)d_in[3];
    const float* aneigh = (const float*)d_in[4];
    float* out = (float*)d_out;

    const int SMEM_DYN = 2 * STAGE_B;  // 81920 B
    cudaFuncSetAttribute(feats_tc, cudaFuncAttributeMaxDynamicSharedMemorySize, SMEM_DYN);
    cudaFuncSetAttribute(out_tc,   cudaFuncAttributeMaxDynamicSharedMemorySize, SMEM_DYN);

    prep_x<<<(NB * NN * NF / 4) / 256, 256>>>(x);
    prep_kT<<<dim3(NFP / 32, NF / 32, NH), dim3(32, 8)>>>(kern);
    w2k<<<(NH * NF) / 8, 256>>>(kern, aself, aneigh);
    s_comp<<<(NB * NN) / 8, 256>>>(x);
    attn_softmax<<<(NH * NB * NN) / 8, 256>>>(out);
    bias_mean<<<NFP / 256, 256>>>(biases);

    feats_tc<<<dim3(NN / 128, NFP / 128, NH * NB), 256, SMEM_DYN>>>();
    out_tc<<<dim3(NFP / 128, NN / 128, NB), 256, SMEM_DYN>>>(out);
}

// round 4
// speedup vs baseline: 5.5988x; 2.0617x over previous
#include <cuda_runtime.h>
#include <cuda_fp16.h>
#include <stdint.h>

#define NH 3
#define NB 16
#define NN 1024
#define NF 512
#define NFP 1024

// ---------------------------------------------------------------------------
// Scratch arena
// ---------------------------------------------------------------------------
#define OFF_XH    0ull            // x fp16            16 MB
#define OFF_KTH   16777216ull     // kernels^T hi fp16  3 MB
#define OFF_KTL   19922944ull     // kernels^T lo fp16  3 MB
#define OFF_FTH   23068672ull     // feats^T fp16      96 MB
#define OFF_AH    123731968ull    // attn fp16         96 MB
#define OFF_W2S   224395264ull
#define OFF_W2N   224401408ull
#define OFF_SS    224407552ull
#define OFF_SN    224604160ull
#define OFF_BM    224800768ull
#define ARENA_SZ  224804864ull

__device__ __align__(128) unsigned char g_arena[ARENA_SZ];
#define AP(T, off) ((T*)(g_arena + (off)))

// ---------------------------------------------------------------------------
// PTX helpers (base sm_103 target)
// ---------------------------------------------------------------------------
__device__ __forceinline__ uint32_t smem_u32(const void* p) {
    uint32_t a;
    asm("{ .reg .u64 t; cvta.to.shared.u64 t, %1; cvt.u32.u64 %0, t; }"
        : "=r"(a) : "l"(p));
    return a;
}
__device__ __forceinline__ void cpasync16(uint32_t s, const void* g) {
    asm volatile("cp.async.cg.shared.global [%0], [%1], 16;"
                 :: "r"(s), "l"(g) : "memory");
}
__device__ __forceinline__ void cp_commit() {
    asm volatile("cp.async.commit_group;" ::: "memory");
}
template <int N>
__device__ __forceinline__ void cp_wait() {
    asm volatile("cp.async.wait_group %0;" :: "n"(N) : "memory");
}
__device__ __forceinline__ void ldsm4(uint32_t* r, uint32_t a) {
    asm volatile("ldmatrix.sync.aligned.m8n8.x4.shared.b16 {%0,%1,%2,%3}, [%4];"
                 : "=r"(r[0]), "=r"(r[1]), "=r"(r[2]), "=r"(r[3]) : "r"(a));
}
__device__ __forceinline__ void ldsm2(uint32_t* r, uint32_t a) {
    asm volatile("ldmatrix.sync.aligned.m8n8.x2.shared.b16 {%0,%1}, [%2];"
                 : "=r"(r[0]), "=r"(r[1]) : "r"(a));
}
__device__ __forceinline__ void mma16816(float* c, const uint32_t* a,
                                         const uint32_t* b) {
    asm volatile(
        "mma.sync.aligned.m16n8k16.row.col.f32.f16.f16.f32 "
        "{%0,%1,%2,%3}, {%4,%5,%6,%7}, {%8,%9}, {%0,%1,%2,%3};"
        : "+f"(c[0]), "+f"(c[1]), "+f"(c[2]), "+f"(c[3])
        : "r"(a[0]), "r"(a[1]), "r"(a[2]), "r"(a[3]), "r"(b[0]), "r"(b[1]));
}

// ---------------------------------------------------------------------------
// feats GEMM: D[fp][node] = sum_f (kT_hi+kT_lo)[fp][f] * x[node][f]
// kc=32, pitch 80B, 3 tiles/stage (Ah, Al, B), 3-stage ring, 1 sync/stage.
// ---------------------------------------------------------------------------
#define FP_PITCH  80
#define F_TILE    10240        // 128 x 80
#define F_STAGE   30720        // 3 tiles
#define F_SMEM    92160        // 3 stages

__device__ __forceinline__ void ld_feats_stage(
    uint32_t st, int tid, const __half* Ah, const __half* Al, const __half* Bx)
{
#pragma unroll
    for (int it = 0; it < 2; it++) {
        const int idx = it * 256 + tid;
        const int row = idx >> 2, seg = idx & 3;
        const uint32_t so = row * FP_PITCH + seg * 16;
        cpasync16(st + so,              (const char*)(Ah + (size_t)row * NF) + seg * 16);
        cpasync16(st + F_TILE + so,     (const char*)(Al + (size_t)row * NF) + seg * 16);
        cpasync16(st + 2 * F_TILE + so, (const char*)(Bx + (size_t)row * NF) + seg * 16);
    }
    cp_commit();
}

__global__ void __launch_bounds__(256, 2) feats_tc() {
    extern __shared__ char dynsm[];
    const int tid = threadIdx.x;
    const int w = tid >> 5, lane = tid & 31;
    const int wm = w & 1, wn = w >> 1;
    const int z = blockIdx.z, h = z >> 4, b = z & 15;
    const int m0 = blockIdx.y * 128, n0 = blockIdx.x * 128;

    const __half* Ah = AP(__half, OFF_KTH) + (size_t)h * NFP * NF + (size_t)m0 * NF;
    const __half* Al = AP(__half, OFF_KTL) + (size_t)h * NFP * NF + (size_t)m0 * NF;
    const __half* Bx = AP(__half, OFF_XH)  + (size_t)b * NN * NF + (size_t)n0 * NF;

    const uint32_t sb = smem_u32(dynsm);
    float acc[4][4][4];
#pragma unroll
    for (int mt = 0; mt < 4; mt++)
#pragma unroll
        for (int nt = 0; nt < 4; nt++)
#pragma unroll
            for (int q = 0; q < 4; q++) acc[mt][nt][q] = 0.f;

    const int S = 16;   // K = 512 / 32
    ld_feats_stage(sb,            tid, Ah,      Al,      Bx);
    ld_feats_stage(sb + F_STAGE,  tid, Ah + 32, Al + 32, Bx + 32);

    for (int s = 0; s < S; s++) {
        if (s < S - 1) cp_wait<1>(); else cp_wait<0>();
        __syncthreads();
        const int sn = s + 2;
        if (sn < S)
            ld_feats_stage(sb + (sn % 3) * F_STAGE, tid,
                           Ah + sn * 32, Al + sn * 32, Bx + sn * 32);
        const uint32_t bu = sb + (s % 3) * F_STAGE;
        const uint32_t Ahb = bu, Alb = bu + F_TILE, Bb = bu + 2 * F_TILE;
#pragma unroll
        for (int ks = 0; ks < 2; ks++) {
            uint32_t bq[4][2];
            const int brow = wn * 32 + (lane & 7);
            const int bcol = ks * 16 + ((lane >> 3) & 1) * 8;
#pragma unroll
            for (int nt = 0; nt < 4; nt++)
                ldsm2(bq[nt], Bb + (uint32_t)(brow + nt * 8) * FP_PITCH + bcol * 2);
            const int arow = wm * 64 + (lane & 15);
            const int acol = ks * 16 + (lane >> 4) * 8;
#pragma unroll
            for (int mt = 0; mt < 4; mt++) {
                uint32_t ah[4], al[4];
                const uint32_t ao = (uint32_t)(arow + mt * 16) * FP_PITCH + acol * 2;
                ldsm4(ah, Ahb + ao);
                ldsm4(al, Alb + ao);
#pragma unroll
                for (int nt = 0; nt < 4; nt++) {
                    mma16816(acc[mt][nt], ah, bq[nt]);
                    mma16816(acc[mt][nt], al, bq[nt]);
                }
            }
        }
    }

    // epilogue: fp16 single into feats^T (K-major for the out GEMM)
    __half* ft = AP(__half, OFF_FTH) + (size_t)z * NFP * NN;
#pragma unroll
    for (int mt = 0; mt < 4; mt++)
#pragma unroll
        for (int nt = 0; nt < 4; nt++)
#pragma unroll
            for (int hf = 0; hf < 2; hf++) {
                const int row = m0 + wm * 64 + mt * 16 + (lane >> 2) + hf * 8;
                const int col = n0 + wn * 32 + nt * 8 + (lane & 3) * 2;
                __half2 p;
                p.x = __float2half(acc[mt][nt][hf * 2 + 0]);
                p.y = __float2half(acc[mt][nt][hf * 2 + 1]);
                *(__half2*)(ft + (size_t)row * NN + col) = p;
            }
}

// ---------------------------------------------------------------------------
// out GEMM: D[node][fp] = sum_h sum_j attn[h,b,node,j] * fT[h,b][fp][j]
// Single fp16 product, kc=64, pitch 144B, 2 tiles/stage, 3-stage ring.
// ---------------------------------------------------------------------------
#define OP_PITCH  144
#define O_TILE    18432        // 128 x 144
#define O_STAGE   36864        // 2 tiles
#define O_SMEM    110592       // 3 stages

__device__ __forceinline__ void ld_out_stage(
    uint32_t st, int tid, const __half* A, const __half* B)
{
#pragma unroll
    for (int it = 0; it < 4; it++) {
        const int idx = it * 256 + tid;
        const int row = idx >> 3, seg = idx & 7;
        const uint32_t so = row * OP_PITCH + seg * 16;
        cpasync16(st + so,          (const char*)(A + (size_t)row * NN) + seg * 16);
        cpasync16(st + O_TILE + so, (const char*)(B + (size_t)row * NN) + seg * 16);
    }
    cp_commit();
}

__global__ void __launch_bounds__(256, 2) out_tc(float* __restrict__ out) {
    extern __shared__ char dynsm[];
    const int tid = threadIdx.x;
    const int w = tid >> 5, lane = tid & 31;
    const int wm = w & 1, wn = w >> 1;
    const int b = blockIdx.z;
    const int m0 = blockIdx.y * 128;   // node tile
    const int n0 = blockIdx.x * 128;   // fp tile

    const size_t hst = (size_t)NB * NN * NN;
    const __half* A0 = AP(__half, OFF_AH)  + ((size_t)b * NN + m0) * NN;
    const __half* B0 = AP(__half, OFF_FTH) + ((size_t)b * NFP + n0) * NN;

    const uint32_t sb = smem_u32(dynsm);
    float acc[4][4][4];
#pragma unroll
    for (int mt = 0; mt < 4; mt++)
#pragma unroll
        for (int nt = 0; nt < 4; nt++)
#pragma unroll
            for (int q = 0; q < 4; q++) acc[mt][nt][q] = 0.f;

    const int S = 48;   // 3 heads x (1024 / 64)
    ld_out_stage(sb,           tid, A0,      B0);
    ld_out_stage(sb + O_STAGE, tid, A0 + 64, B0 + 64);

    for (int s = 0; s < S; s++) {
        if (s < S - 1) cp_wait<1>(); else cp_wait<0>();
        __syncthreads();
        const int sn = s + 2;
        if (sn < S) {
            const int hh = sn >> 4, kt = (sn & 15) * 64;
            ld_out_stage(sb + (sn % 3) * O_STAGE, tid,
                         A0 + hh * hst + kt, B0 + hh * hst + kt);
        }
        const uint32_t bu = sb + (s % 3) * O_STAGE;
        const uint32_t Ab = bu, Bb = bu + O_TILE;
#pragma unroll
        for (int ks = 0; ks < 4; ks++) {
            uint32_t bq[4][2];
            const int brow = wn * 32 + (lane & 7);
            const int bcol = ks * 16 + ((lane >> 3) & 1) * 8;
#pragma unroll
            for (int nt = 0; nt < 4; nt++)
                ldsm2(bq[nt], Bb + (uint32_t)(brow + nt * 8) * OP_PITCH + bcol * 2);
            const int arow = wm * 64 + (lane & 15);
            const int acol = ks * 16 + (lane >> 4) * 8;
#pragma unroll
            for (int mt = 0; mt < 4; mt++) {
                uint32_t aq[4];
                ldsm4(aq, Ab + (uint32_t)(arow + mt * 16) * OP_PITCH + acol * 2);
#pragma unroll
                for (int nt = 0; nt < 4; nt++)
                    mma16816(acc[mt][nt], aq, bq[nt]);
            }
        }
    }

    const float* bm = AP(float, OFF_BM);
    float* C = out + ((size_t)(NH * NB) + b) * NN * NN;
#pragma unroll
    for (int mt = 0; mt < 4; mt++)
#pragma unroll
        for (int nt = 0; nt < 4; nt++)
#pragma unroll
            for (int hf = 0; hf < 2; hf++) {
                const int row = m0 + wm * 64 + mt * 16 + (lane >> 2) + hf * 8;
                const int col = n0 + wn * 32 + nt * 8 + (lane & 3) * 2;
                float2 v;
                v.x = acc[mt][nt][hf * 2 + 0] * (1.f / 3.f) + bm[col + 0];
                v.y = acc[mt][nt][hf * 2 + 1] * (1.f / 3.f) + bm[col + 1];
                *(float2*)(C + (size_t)row * NN + col) = v;
            }
}

// ---------------------------------------------------------------------------
// Prep kernels
// ---------------------------------------------------------------------------
__global__ void prep_x(const float* __restrict__ x) {
    const size_t i = (size_t)blockIdx.x * 256 + threadIdx.x;  // NB*NN*NF/4
    float4 v = ((const float4*)x)[i];
    union { __half h[4]; uint2 u; } o;
    o.h[0] = __float2half(v.x); o.h[1] = __float2half(v.y);
    o.h[2] = __float2half(v.z); o.h[3] = __float2half(v.w);
    ((uint2*)AP(unsigned char, OFF_XH))[i] = o.u;
}

// kernels (H, F, F_) -> kT (H, F_, F), fp16 hi/lo split
__global__ void prep_kT(const float* __restrict__ kern) {
    __shared__ float t[32][33];
    const int h = blockIdx.z;
    const int fp0 = blockIdx.x * 32, f0 = blockIdx.y * 32;
    const float* src = kern + (size_t)h * NF * NFP;
#pragma unroll
    for (int j = 0; j < 4; j++)
        t[threadIdx.y + j * 8][threadIdx.x] =
            src[(size_t)(f0 + threadIdx.y + j * 8) * NFP + fp0 + threadIdx.x];
    __syncthreads();
    __half* dhi = AP(__half, OFF_KTH) + (size_t)h * NFP * NF;
    __half* dlo = AP(__half, OFF_KTL) + (size_t)h * NFP * NF;
#pragma unroll
    for (int j = 0; j < 4; j++) {
        float v = t[threadIdx.x][threadIdx.y + j * 8];
        __half hi = __float2half(v);
        size_t o = (size_t)(fp0 + threadIdx.y + j * 8) * NF + f0 + threadIdx.x;
        dhi[o] = hi;
        dlo[o] = __float2half(v - __half2float(hi));
    }
}

// w2[h][f] = sum_fp kernels[h][f][fp] * a[h][fp]
__global__ void w2k(const float* __restrict__ kern,
                    const float* __restrict__ as, const float* __restrict__ an) {
    const int gw = blockIdx.x * 8 + (threadIdx.x >> 5);
    const int lane = threadIdx.x & 31;
    const int h = gw >> 9, f = gw & 511;
    const float* row = kern + ((size_t)h * NF + f) * NFP;
    const float* a1 = as + (size_t)h * NFP;
    const float* a2 = an + (size_t)h * NFP;
    float s1 = 0.f, s2 = 0.f;
#pragma unroll
    for (int it = 0; it < 8; it++) {
        int k = it * 128 + lane * 4;
        float4 kv = *(const float4*)(row + k);
        float4 v1 = *(const float4*)(a1 + k);
        float4 v2 = *(const float4*)(a2 + k);
        s1 += kv.x * v1.x + kv.y * v1.y + kv.z * v1.z + kv.w * v1.w;
        s2 += kv.x * v2.x + kv.y * v2.y + kv.z * v2.z + kv.w * v2.w;
    }
#pragma unroll
    for (int o = 16; o > 0; o >>= 1) {
        s1 += __shfl_xor_sync(0xFFFFFFFFu, s1, o);
        s2 += __shfl_xor_sync(0xFFFFFFFFu, s2, o);
    }
    if (lane == 0) {
        AP(float, OFF_W2S)[(size_t)h * NF + f] = s1;
        AP(float, OFF_W2N)[(size_t)h * NF + f] = s2;
    }
}

// s_self[h,b,n] = x[b,n,:] . w2s[h]; s_neigh likewise
__global__ void __launch_bounds__(256) s_comp(const float* __restrict__ x) {
    __shared__ float ws[NH * NF], wn_[NH * NF];
    for (int i = threadIdx.x; i < NH * NF; i += 256) {
        ws[i]  = AP(float, OFF_W2S)[i];
        wn_[i] = AP(float, OFF_W2N)[i];
    }
    __syncthreads();
    const int gw = blockIdx.x * 8 + (threadIdx.x >> 5);
    const int lane = threadIdx.x & 31;
    const int b = gw >> 10, n = gw & 1023;
    const float* xr = x + ((size_t)b * NN + n) * NF;
    float a[3] = {0.f, 0.f, 0.f}, c[3] = {0.f, 0.f, 0.f};
#pragma unroll
    for (int it = 0; it < 4; it++) {
        int f = it * 128 + lane * 4;
        float4 xv = *(const float4*)(xr + f);
#pragma unroll
        for (int h = 0; h < 3; h++) {
            float4 w = *(const float4*)&ws[h * NF + f];
            float4 u = *(const float4*)&wn_[h * NF + f];
            a[h] += xv.x * w.x + xv.y * w.y + xv.z * w.z + xv.w * w.w;
            c[h] += xv.x * u.x + xv.y * u.y + xv.z * u.z + xv.w * u.w;
        }
    }
#pragma unroll
    for (int h = 0; h < 3; h++) {
#pragma unroll
        for (int o = 16; o > 0; o >>= 1) {
            a[h] += __shfl_xor_sync(0xFFFFFFFFu, a[h], o);
            c[h] += __shfl_xor_sync(0xFFFFFFFFu, c[h], o);
        }
    }
    if (lane == 0) {
#pragma unroll
        for (int h = 0; h < 3; h++) {
            AP(float, OFF_SS)[(size_t)h * NB * NN + b * NN + n] = a[h];
            AP(float, OFF_SN)[(size_t)h * NB * NN + b * NN + n] = c[h];
        }
    }
}

// Row softmax of leaky(s_self[i]+s_neigh[j]); fp32 attn to d_out + fp16 copy.
__global__ void __launch_bounds__(256) attn_softmax(float* __restrict__ out) {
    __shared__ float c[NN];
    const int w    = threadIdx.x >> 5;
    const int lane = threadIdx.x & 31;
    const size_t r0 = (size_t)blockIdx.x * 8;
    const size_t hb = r0 >> 10;
    const float* cn = AP(float, OFF_SN) + hb * NN;
    for (int i = threadIdx.x; i < NN; i += 256) c[i] = cn[i];
    __syncthreads();

    const size_t r = r0 + w;
    const float a = AP(float, OFF_SS)[r];

    float ev[32];
    float m = -1e30f;
#pragma unroll
    for (int it = 0; it < 32; it++) {
        float t = a + c[it * 32 + lane];
        t = (t >= 0.f) ? t : 0.2f * t;
        ev[it] = t;
        m = fmaxf(m, t);
    }
#pragma unroll
    for (int o = 16; o > 0; o >>= 1) m = fmaxf(m, __shfl_xor_sync(0xFFFFFFFFu, m, o));
    float s = 0.f;
#pragma unroll
    for (int it = 0; it < 32; it++) {
        float e = __expf(ev[it] - m);
        ev[it] = e;
        s += e;
    }
#pragma unroll
    for (int o = 16; o > 0; o >>= 1) s += __shfl_xor_sync(0xFFFFFFFFu, s, o);
    const float inv = 1.f / s;

    float* orow = out + r * NN;
    __half* ah = AP(__half, OFF_AH) + r * NN;
#pragma unroll
    for (int it = 0; it < 32; it++) {
        float v = ev[it] * inv;
        int col = it * 32 + lane;
        orow[col] = v;
        ah[col] = __float2half(v);
    }
}

__global__ void bias_mean(const float* __restrict__ biases) {
    int k = blockIdx.x * 256 + threadIdx.x;
    AP(float, OFF_BM)[k] =
        (biases[k] + biases[NFP + k] + biases[2 * NFP + k]) * (1.f / 3.f);
}

// ---------------------------------------------------------------------------
extern "C" void kernel_launch(void* const* d_in, const int* in_sizes, int n_in,
                              void* d_out, int out_size)
{
    const float* x      = (const float*)d_in[0];
    const float* kern   = (const float*)d_in[1];
    const float* biases = (const float*)d_in[2];
    const float* aself  = (const float*)d_in[3];
    const float* aneigh = (const float*)d_in[4];
    float* out = (float*)d_out;

    cudaFuncSetAttribute(feats_tc, cudaFuncAttributeMaxDynamicSharedMemorySize, F_SMEM);
    cudaFuncSetAttribute(out_tc,   cudaFuncAttributeMaxDynamicSharedMemorySize, O_SMEM);

    prep_x<<<(NB * NN * NF / 4) / 256, 256>>>(x);
    prep_kT<<<dim3(NFP / 32, NF / 32, NH), dim3(32, 8)>>>(kern);
    w2k<<<(NH * NF) / 8, 256>>>(kern, aself, aneigh);
    s_comp<<<(NB * NN) / 8, 256>>>(x);
    attn_softmax<<<(NH * NB * NN) / 8, 256>>>(out);
    bias_mean<<<NFP / 256, 256>>>(biases);

    feats_tc<<<dim3(NN / 128, NFP / 128, NH * NB), 256, F_SMEM>>>();
    out_tc<<<dim3(NFP / 128, NN / 128, NB), 256, O_SMEM>>>(out);
}

// round 5
// speedup vs baseline: 7.1975x; 1.2855x over previous
#include <cuda_runtime.h>
#include <cuda_fp16.h>
#include <stdint.h>

#define NH 3
#define NB 16
#define NN 1024
#define NF 512
#define NFP 1024

// ---------------------------------------------------------------------------
// Scratch arena
// ---------------------------------------------------------------------------
#define OFF_XH    0ull            // x fp16            16 MB
#define OFF_KTH   16777216ull     // kernels^T fp16     3 MB
#define OFF_FTH   19922944ull     // feats^T fp16      96 MB
#define OFF_AH    120586240ull    // attn fp16         96 MB
#define OFF_W2S   221249536ull
#define OFF_W2N   221255680ull
#define OFF_SS    221261824ull
#define OFF_SN    221458432ull
#define OFF_BM    221655040ull
#define ARENA_SZ  221659136ull

__device__ __align__(128) unsigned char g_arena[ARENA_SZ];
#define AP(T, off) ((T*)(g_arena + (off)))

// ---------------------------------------------------------------------------
// PTX helpers (base sm_103 target)
// ---------------------------------------------------------------------------
__device__ __forceinline__ uint32_t smem_u32(const void* p) {
    uint32_t a;
    asm("{ .reg .u64 t; cvta.to.shared.u64 t, %1; cvt.u32.u64 %0, t; }"
        : "=r"(a) : "l"(p));
    return a;
}
__device__ __forceinline__ void cpasync16(uint32_t s, const void* g) {
    asm volatile("cp.async.cg.shared.global [%0], [%1], 16;"
                 :: "r"(s), "l"(g) : "memory");
}
__device__ __forceinline__ void cp_commit() {
    asm volatile("cp.async.commit_group;" ::: "memory");
}
template <int N>
__device__ __forceinline__ void cp_wait() {
    asm volatile("cp.async.wait_group %0;" :: "n"(N) : "memory");
}
__device__ __forceinline__ void ldsm4(uint32_t* r, uint32_t a) {
    asm volatile("ldmatrix.sync.aligned.m8n8.x4.shared.b16 {%0,%1,%2,%3}, [%4];"
                 : "=r"(r[0]), "=r"(r[1]), "=r"(r[2]), "=r"(r[3]) : "r"(a));
}
__device__ __forceinline__ void mma16816(float* c, const uint32_t* a,
                                         const uint32_t* b) {
    asm volatile(
        "mma.sync.aligned.m16n8k16.row.col.f32.f16.f16.f32 "
        "{%0,%1,%2,%3}, {%4,%5,%6,%7}, {%8,%9}, {%0,%1,%2,%3};"
        : "+f"(c[0]), "+f"(c[1]), "+f"(c[2]), "+f"(c[3])
        : "r"(a[0]), "r"(a[1]), "r"(a[2]), "r"(a[3]), "r"(b[0]), "r"(b[1]));
}

// ---------------------------------------------------------------------------
// Unified GEMM core: 128x128 CTA tile, kc=64, A/B K-major fp16.
// Smem: 2 tiles/stage (A, B), 128 rows x 144B pitch, 3-stage ring, 1 sync/stage.
// Warp tile 64x32 (2x4 warp grid), B fragments fetched pairwise via ldmatrix.x4.
// ---------------------------------------------------------------------------
#define GP_PITCH  144
#define G_TILE    18432        // 128 x 144
#define G_STAGE   36864        // 2 tiles
#define G_SMEM    110592       // 3 stages

__device__ __forceinline__ void ld_stage(
    uint32_t st, int tid, const __half* A, const __half* B, int lda, int ldb)
{
#pragma unroll
    for (int it = 0; it < 4; it++) {
        const int idx = it * 256 + tid;
        const int row = idx >> 3, seg = idx & 7;
        const uint32_t so = row * GP_PITCH + seg * 16;
        cpasync16(st + so,          (const char*)(A + (size_t)row * lda) + seg * 16);
        cpasync16(st + G_TILE + so, (const char*)(B + (size_t)row * ldb) + seg * 16);
    }
    cp_commit();
}

// S = total kc-stages; KPH = stages per head; hst = per-head element stride.
template <int S, int KPH>
__device__ __forceinline__ void gemm_mma(
    const __half* A0, const __half* B0, size_t hst, int lda, int ldb,
    uint32_t sb, float acc[4][4][4], int wm, int wn, int lane, int tid)
{
#pragma unroll
    for (int mt = 0; mt < 4; mt++)
#pragma unroll
        for (int nt = 0; nt < 4; nt++)
#pragma unroll
            for (int q = 0; q < 4; q++) acc[mt][nt][q] = 0.f;

    ld_stage(sb,           tid, A0,      B0,      lda, ldb);
    ld_stage(sb + G_STAGE, tid, A0 + 64, B0 + 64, lda, ldb);

    for (int s = 0; s < S; s++) {
        if (s < S - 1) cp_wait<1>(); else cp_wait<0>();
        __syncthreads();
        const int sn = s + 2;
        if (sn < S) {
            const int hh = sn / KPH, kt = (sn % KPH) * 64;
            ld_stage(sb + (sn % 3) * G_STAGE, tid,
                     A0 + hh * hst + kt, B0 + hh * hst + kt, lda, ldb);
        }
        const uint32_t bu = sb + (s % 3) * G_STAGE;
        const uint32_t Ab = bu, Bb = bu + G_TILE;
#pragma unroll
        for (int ks = 0; ks < 4; ks++) {
            // B: two ldmatrix.x4, each serving two n-tiles' {k0,k8} fragments.
            uint32_t bq[4][2];
            const int bcol = ks * 16 + (((lane >> 3) & 1) << 3);
            const int brow_in = ((lane >> 4) << 3) + (lane & 7);
#pragma unroll
            for (int p = 0; p < 2; p++) {
                uint32_t r[4];
                const int brow = wn * 32 + p * 16 + brow_in;
                ldsm4(r, Bb + (uint32_t)brow * GP_PITCH + bcol * 2);
                bq[2 * p][0] = r[0]; bq[2 * p][1] = r[1];
                bq[2 * p + 1][0] = r[2]; bq[2 * p + 1][1] = r[3];
            }
            const int arow = wm * 64 + (lane & 15);
            const int acol = ks * 16 + (lane >> 4) * 8;
#pragma unroll
            for (int mt = 0; mt < 4; mt++) {
                uint32_t aq[4];
                ldsm4(aq, Ab + (uint32_t)(arow + mt * 16) * GP_PITCH + acol * 2);
#pragma unroll
                for (int nt = 0; nt < 4; nt++)
                    mma16816(acc[mt][nt], aq, bq[nt]);
            }
        }
    }
}

// ---------------------------------------------------------------------------
// feats GEMM: D[fp][node] = sum_f kT[fp][f] * x[node][f]   (single fp16)
// ---------------------------------------------------------------------------
__global__ void __launch_bounds__(256, 2) feats_tc() {
    extern __shared__ char dynsm[];
    const int tid = threadIdx.x;
    const int w = tid >> 5, lane = tid & 31;
    const int wm = w & 1, wn = w >> 1;
    const int z = blockIdx.z, h = z >> 4, b = z & 15;
    const int m0 = blockIdx.y * 128, n0 = blockIdx.x * 128;

    const __half* A0 = AP(__half, OFF_KTH) + (size_t)h * NFP * NF + (size_t)m0 * NF;
    const __half* B0 = AP(__half, OFF_XH)  + (size_t)b * NN * NF + (size_t)n0 * NF;

    float acc[4][4][4];
    gemm_mma<8, 8>(A0, B0, 0, NF, NF, smem_u32(dynsm), acc, wm, wn, lane, tid);

    __half* ft = AP(__half, OFF_FTH) + (size_t)z * NFP * NN;
#pragma unroll
    for (int mt = 0; mt < 4; mt++)
#pragma unroll
        for (int nt = 0; nt < 4; nt++)
#pragma unroll
            for (int hf = 0; hf < 2; hf++) {
                const int row = m0 + wm * 64 + mt * 16 + (lane >> 2) + hf * 8;
                const int col = n0 + wn * 32 + nt * 8 + (lane & 3) * 2;
                __half2 p;
                p.x = __float2half(acc[mt][nt][hf * 2 + 0]);
                p.y = __float2half(acc[mt][nt][hf * 2 + 1]);
                *(__half2*)(ft + (size_t)row * NN + col) = p;
            }
}

// ---------------------------------------------------------------------------
// out GEMM: D[node][fp] = sum_h sum_j attn[h,b,node,j] * fT[h,b][fp][j]
// ---------------------------------------------------------------------------
__global__ void __launch_bounds__(256, 2) out_tc(float* __restrict__ out) {
    extern __shared__ char dynsm[];
    const int tid = threadIdx.x;
    const int w = tid >> 5, lane = tid & 31;
    const int wm = w & 1, wn = w >> 1;
    const int b = blockIdx.z;
    const int m0 = blockIdx.y * 128;   // node tile
    const int n0 = blockIdx.x * 128;   // fp tile

    const size_t hst = (size_t)NB * NN * NN;
    const __half* A0 = AP(__half, OFF_AH)  + ((size_t)b * NN + m0) * NN;
    const __half* B0 = AP(__half, OFF_FTH) + ((size_t)b * NFP + n0) * NN;

    float acc[4][4][4];
    gemm_mma<48, 16>(A0, B0, hst, NN, NN, smem_u32(dynsm), acc, wm, wn, lane, tid);

    const float* bm = AP(float, OFF_BM);
    float* C = out + ((size_t)(NH * NB) + b) * NN * NN;
#pragma unroll
    for (int mt = 0; mt < 4; mt++)
#pragma unroll
        for (int nt = 0; nt < 4; nt++)
#pragma unroll
            for (int hf = 0; hf < 2; hf++) {
                const int row = m0 + wm * 64 + mt * 16 + (lane >> 2) + hf * 8;
                const int col = n0 + wn * 32 + nt * 8 + (lane & 3) * 2;
                float2 v;
                v.x = acc[mt][nt][hf * 2 + 0] * (1.f / 3.f) + bm[col + 0];
                v.y = acc[mt][nt][hf * 2 + 1] * (1.f / 3.f) + bm[col + 1];
                *(float2*)(C + (size_t)row * NN + col) = v;
            }
}

// ---------------------------------------------------------------------------
// Prep kernels
// ---------------------------------------------------------------------------
__global__ void prep_x(const float* __restrict__ x) {
    const size_t i = (size_t)blockIdx.x * 256 + threadIdx.x;  // NB*NN*NF/4
    float4 v = ((const float4*)x)[i];
    union { __half h[4]; uint2 u; } o;
    o.h[0] = __float2half(v.x); o.h[1] = __float2half(v.y);
    o.h[2] = __float2half(v.z); o.h[3] = __float2half(v.w);
    ((uint2*)AP(unsigned char, OFF_XH))[i] = o.u;
}

// kernels (H, F, F_) -> kT (H, F_, F) fp16
__global__ void prep_kT(const float* __restrict__ kern) {
    __shared__ float t[32][33];
    const int h = blockIdx.z;
    const int fp0 = blockIdx.x * 32, f0 = blockIdx.y * 32;
    const float* src = kern + (size_t)h * NF * NFP;
#pragma unroll
    for (int j = 0; j < 4; j++)
        t[threadIdx.y + j * 8][threadIdx.x] =
            src[(size_t)(f0 + threadIdx.y + j * 8) * NFP + fp0 + threadIdx.x];
    __syncthreads();
    __half* dst = AP(__half, OFF_KTH) + (size_t)h * NFP * NF;
#pragma unroll
    for (int j = 0; j < 4; j++) {
        float v = t[threadIdx.x][threadIdx.y + j * 8];
        dst[(size_t)(fp0 + threadIdx.y + j * 8) * NF + f0 + threadIdx.x] =
            __float2half(v);
    }
}

// w2[h][f] = sum_fp kernels[h][f][fp] * a[h][fp]
__global__ void w2k(const float* __restrict__ kern,
                    const float* __restrict__ as, const float* __restrict__ an) {
    const int gw = blockIdx.x * 8 + (threadIdx.x >> 5);
    const int lane = threadIdx.x & 31;
    const int h = gw >> 9, f = gw & 511;
    const float* row = kern + ((size_t)h * NF + f) * NFP;
    const float* a1 = as + (size_t)h * NFP;
    const float* a2 = an + (size_t)h * NFP;
    float s1 = 0.f, s2 = 0.f;
#pragma unroll
    for (int it = 0; it < 8; it++) {
        int k = it * 128 + lane * 4;
        float4 kv = *(const float4*)(row + k);
        float4 v1 = *(const float4*)(a1 + k);
        float4 v2 = *(const float4*)(a2 + k);
        s1 += kv.x * v1.x + kv.y * v1.y + kv.z * v1.z + kv.w * v1.w;
        s2 += kv.x * v2.x + kv.y * v2.y + kv.z * v2.z + kv.w * v2.w;
    }
#pragma unroll
    for (int o = 16; o > 0; o >>= 1) {
        s1 += __shfl_xor_sync(0xFFFFFFFFu, s1, o);
        s2 += __shfl_xor_sync(0xFFFFFFFFu, s2, o);
    }
    if (lane == 0) {
        AP(float, OFF_W2S)[(size_t)h * NF + f] = s1;
        AP(float, OFF_W2N)[(size_t)h * NF + f] = s2;
    }
}

// s_self[h,b,n] = x[b,n,:] . w2s[h]; s_neigh likewise
__global__ void __launch_bounds__(256) s_comp(const float* __restrict__ x) {
    __shared__ float ws[NH * NF], wn_[NH * NF];
    for (int i = threadIdx.x; i < NH * NF; i += 256) {
        ws[i]  = AP(float, OFF_W2S)[i];
        wn_[i] = AP(float, OFF_W2N)[i];
    }
    __syncthreads();
    const int gw = blockIdx.x * 8 + (threadIdx.x >> 5);
    const int lane = threadIdx.x & 31;
    const int b = gw >> 10, n = gw & 1023;
    const float* xr = x + ((size_t)b * NN + n) * NF;
    float a[3] = {0.f, 0.f, 0.f}, c[3] = {0.f, 0.f, 0.f};
#pragma unroll
    for (int it = 0; it < 4; it++) {
        int f = it * 128 + lane * 4;
        float4 xv = *(const float4*)(xr + f);
#pragma unroll
        for (int h = 0; h < 3; h++) {
            float4 w = *(const float4*)&ws[h * NF + f];
            float4 u = *(const float4*)&wn_[h * NF + f];
            a[h] += xv.x * w.x + xv.y * w.y + xv.z * w.z + xv.w * w.w;
            c[h] += xv.x * u.x + xv.y * u.y + xv.z * u.z + xv.w * u.w;
        }
    }
#pragma unroll
    for (int h = 0; h < 3; h++) {
#pragma unroll
        for (int o = 16; o > 0; o >>= 1) {
            a[h] += __shfl_xor_sync(0xFFFFFFFFu, a[h], o);
            c[h] += __shfl_xor_sync(0xFFFFFFFFu, c[h], o);
        }
    }
    if (lane == 0) {
#pragma unroll
        for (int h = 0; h < 3; h++) {
            AP(float, OFF_SS)[(size_t)h * NB * NN + b * NN + n] = a[h];
            AP(float, OFF_SN)[(size_t)h * NB * NN + b * NN + n] = c[h];
        }
    }
}

// Row softmax of leaky(s_self[i]+s_neigh[j]); fp32 attn to d_out + fp16 copy.
__global__ void __launch_bounds__(256) attn_softmax(float* __restrict__ out) {
    __shared__ float c[NN];
    const int w    = threadIdx.x >> 5;
    const int lane = threadIdx.x & 31;
    const size_t r0 = (size_t)blockIdx.x * 8;
    const size_t hb = r0 >> 10;
    const float* cn = AP(float, OFF_SN) + hb * NN;
    for (int i = threadIdx.x; i < NN; i += 256) c[i] = cn[i];
    __syncthreads();

    const size_t r = r0 + w;
    const float a = AP(float, OFF_SS)[r];

    float ev[32];
    float m = -1e30f;
#pragma unroll
    for (int it = 0; it < 32; it++) {
        float t = a + c[it * 32 + lane];
        t = (t >= 0.f) ? t : 0.2f * t;
        ev[it] = t;
        m = fmaxf(m, t);
    }
#pragma unroll
    for (int o = 16; o > 0; o >>= 1) m = fmaxf(m, __shfl_xor_sync(0xFFFFFFFFu, m, o));
    float s = 0.f;
#pragma unroll
    for (int it = 0; it < 32; it++) {
        float e = __expf(ev[it] - m);
        ev[it] = e;
        s += e;
    }
#pragma unroll
    for (int o = 16; o > 0; o >>= 1) s += __shfl_xor_sync(0xFFFFFFFFu, s, o);
    const float inv = 1.f / s;

    float* orow = out + r * NN;
    __half* ah = AP(__half, OFF_AH) + r * NN;
#pragma unroll
    for (int it = 0; it < 32; it++) {
        float v = ev[it] * inv;
        int col = it * 32 + lane;
        orow[col] = v;
        ah[col] = __float2half(v);
    }
}

__global__ void bias_mean(const float* __restrict__ biases) {
    int k = blockIdx.x * 256 + threadIdx.x;
    AP(float, OFF_BM)[k] =
        (biases[k] + biases[NFP + k] + biases[2 * NFP + k]) * (1.f / 3.f);
}

// ---------------------------------------------------------------------------
extern "C" void kernel_launch(void* const* d_in, const int* in_sizes, int n_in,
                              void* d_out, int out_size)
{
    const float* x      = (const float*)d_in[0];
    const float* kern   = (const float*)d_in[1];
    const float* biases = (const float*)d_in[2];
    const float* aself  = (const float*)d_in[3];
    const float* aneigh = (const float*)d_in[4];
    float* out = (float*)d_out;

    cudaFuncSetAttribute(feats_tc, cudaFuncAttributeMaxDynamicSharedMemorySize, G_SMEM);
    cudaFuncSetAttribute(out_tc,   cudaFuncAttributeMaxDynamicSharedMemorySize, G_SMEM);

    prep_x<<<(NB * NN * NF / 4) / 256, 256>>>(x);
    prep_kT<<<dim3(NFP / 32, NF / 32, NH), dim3(32, 8)>>>(kern);
    w2k<<<(NH * NF) / 8, 256>>>(kern, aself, aneigh);
    s_comp<<<(NB * NN) / 8, 256>>>(x);
    attn_softmax<<<(NH * NB * NN) / 8, 256>>>(out);
    bias_mean<<<NFP / 256, 256>>>(biases);

    feats_tc<<<dim3(NN / 128, NFP / 128, NH * NB), 256, G_SMEM>>>();
    out_tc<<<dim3(NFP / 128, NN / 128, NB), 256, G_SMEM>>>(out);
}